// round 2
// baseline (speedup 1.0000x reference)
#include <cuda_runtime.h>
#include <math.h>

#define D_DIM 1024
#define B_DIM 8
#define T_DIM 1024
#define EPC 8            // e-rows per CTA
#define NCTA 128
#define SPECTRAL_RADIUS 0.999f
#define EPS_F 1e-8f

// ------------------------- device scratch (no allocs allowed) ----------------
__device__ float g_p[6][D_DIM];          // power-iteration vectors (unnormalized)
__device__ float g_scale;                // final W multiplier
__device__ int   g_flag[T_DIM][NCTA];    // per-step per-CTA completion flags

// ------------------------- PTX helpers ---------------------------------------
__device__ __forceinline__ int ld_acquire(const int* p) {
    int v;
    asm volatile("ld.acquire.gpu.global.b32 %0, [%1];" : "=r"(v) : "l"(p) : "memory");
    return v;
}
__device__ __forceinline__ void st_release(int* p, int v) {
    asm volatile("st.release.gpu.global.b32 [%0], %1;" :: "l"(p), "r"(v) : "memory");
}
__device__ __forceinline__ void cp16(void* s, const void* g) {
    unsigned sa = (unsigned)__cvta_generic_to_shared(s);
    asm volatile("cp.async.cg.shared.global [%0], [%1], 16;" :: "r"(sa), "l"(g));
}
__device__ __forceinline__ void cp_commit() { asm volatile("cp.async.commit_group;"); }
__device__ __forceinline__ void cp_wait0()  { asm volatile("cp.async.wait_group 0;" ::: "memory"); }
// packed fp32x2 FMA (FFMA2) — doubles fp32 math per instruction on sm_103a
__device__ __forceinline__ void ffma2(unsigned long long& acc, unsigned long long a,
                                      unsigned long long b) {
    asm("fma.rn.f32x2 %0, %1, %2, %0;" : "+l"(acc) : "l"(a), "l"(b));
}
__device__ __forceinline__ float unpack_sum(unsigned long long v) {
    float2 f;
    asm("mov.b64 {%0,%1}, %2;" : "=f"(f.x), "=f"(f.y) : "l"(v));
    return f.x + f.y;
}

// ------------------------- power iteration matvecs ---------------------------
__global__ void mv_T_kernel(const float* __restrict__ W, const float* __restrict__ vin,
                            float* __restrict__ vout) {
    int dl = threadIdx.x >> 5;
    int lane = threadIdx.x & 31;
    int d = blockIdx.x * 8 + dl;
    float acc = 0.f;
    for (int e = lane; e < D_DIM; e += 32)
        acc += W[(size_t)e * D_DIM + d] * vin[e];
    #pragma unroll
    for (int off = 16; off; off >>= 1)
        acc += __shfl_down_sync(0xffffffffu, acc, off);
    if (lane == 0) vout[d] = acc;
}

__global__ void mv_N_kernel(const float* __restrict__ W, const float* __restrict__ vin,
                            float* __restrict__ vout) {
    int el = threadIdx.x >> 5;
    int lane = threadIdx.x & 31;
    int e = blockIdx.x * 8 + el;
    float acc = 0.f;
    const float* row = W + (size_t)e * D_DIM;
    for (int d = lane; d < D_DIM; d += 32)
        acc += row[d] * vin[d];
    #pragma unroll
    for (int off = 16; off; off >>= 1)
        acc += __shfl_down_sync(0xffffffffu, acc, off);
    if (lane == 0) vout[e] = acc;
}

__global__ void finalize_kernel() {
    __shared__ float red[256];
    __shared__ float ssq[6];
    int tid = threadIdx.x;
    for (int v = 0; v < 6; v++) {
        float local = 0.f;
        for (int i = tid; i < D_DIM; i += 256) {
            float x = g_p[v][i];
            local += x * x;
        }
        red[tid] = local;
        __syncthreads();
        for (int s = 128; s; s >>= 1) {
            if (tid < s) red[tid] += red[tid + s];
            __syncthreads();
        }
        if (tid == 0) ssq[v] = red[0];
        __syncthreads();
    }
    if (tid == 0) {
        float a1 = 1.f / (sqrtf(ssq[0]) + EPS_F);
        float b1 = a1 / (a1 * sqrtf(ssq[1]) + EPS_F);
        float a2 = b1 / (b1 * sqrtf(ssq[2]) + EPS_F);
        float b2 = a2 / (a2 * sqrtf(ssq[3]) + EPS_F);
        float a3 = b2 / (b2 * sqrtf(ssq[4]) + EPS_F);
        float b3 = a3 / (a3 * sqrtf(ssq[5]) + EPS_F);
        float sigma = fabsf(a3 * b3 * ssq[5]);
        g_scale = SPECTRAL_RADIUS / (sigma + EPS_F);
    }
}

// ------------------------- persistent sequential scan ------------------------
// h_t = W_eff (x_t + h_{t-1}) + b ; h buffer (out_h) holds h[0..T].
// W rows live in REGISTERS (stationary across t). x streams via cp.async.
__global__ void __launch_bounds__(256, 1)
scan_kernel(const float* __restrict__ x, const float* __restrict__ W,
            const float* __restrict__ bias, float* __restrict__ out_h) {
    extern __shared__ float sm[];
    float* x_s   = sm;                       // 2 * 8192 floats (double buffer)
    float* red_s = sm + 2 * B_DIM * D_DIM;   // 128 floats
    __shared__ float bias_s[EPC];

    int tid = threadIdx.x;
    int e0 = blockIdx.x * EPC;
    float scale = g_scale;

    int tile = tid >> 6;             // 0..3
    int l64  = tid & 63;
    int bt = (tile & 1) * 4;
    int et = (tile >> 1) * 4;
    int wit = (tid >> 5) & 1;

    // Load this thread's W slice into registers (pre-scaled, packed f32x2).
    unsigned long long wreg[4][4][2];
    #pragma unroll
    for (int k = 0; k < 4; k++) {
        #pragma unroll
        for (int j = 0; j < 4; j++) {
            float4 w4 = *(const float4*)(W + (size_t)(e0 + et + j) * D_DIM + l64 * 4 + k * 256);
            w4.x *= scale; w4.y *= scale; w4.z *= scale; w4.w *= scale;
            ulonglong2 u = *reinterpret_cast<ulonglong2*>(&w4);
            wreg[k][j][0] = u.x;
            wreg[k][j][1] = u.y;
        }
    }
    if (tid < EPC) bias_s[tid] = bias[e0 + tid];

    // Prefetch x[0] into buffer 0.
    #pragma unroll
    for (int r = 0; r < 8; r++) {
        int idx = tid + r * 256;
        cp16(x_s + idx * 4, x + (size_t)idx * 4);
    }
    cp_commit();

    int buf = 0;
    for (int t = 0; t < T_DIM; ++t) {
        // Wait for h[t] from all CTAs (parallel acquire-poll, one flag each).
        if (t > 0) {
            if (tid < NCTA) {
                const int* fp = &g_flag[t - 1][tid];
                while (ld_acquire(fp) == 0) { }
            }
        }
        cp_wait0();               // x[t] resident in x_s[buf]
        __syncthreads();

        // s = x[t] + h[t], in place in x_s[buf].
        float* sb = x_s + buf * (B_DIM * D_DIM);
        const float4* hp = (const float4*)(out_h + (size_t)t * B_DIM * D_DIM);
        #pragma unroll
        for (int r = 0; r < 8; r++) {
            int idx = tid + r * 256;
            float4 hv = hp[idx];
            float4 xv = *(float4*)(sb + idx * 4);
            xv.x += hv.x; xv.y += hv.y; xv.z += hv.z; xv.w += hv.w;
            *(float4*)(sb + idx * 4) = xv;
        }
        // Prefetch x[t+1] into the other buffer (overlaps with the dot below).
        if (t + 1 < T_DIM) {
            const float* xn = x + (size_t)(t + 1) * B_DIM * D_DIM;
            float* pb = x_s + (buf ^ 1) * (B_DIM * D_DIM);
            #pragma unroll
            for (int r = 0; r < 8; r++) {
                int idx = tid + r * 256;
                cp16(pb + idx * 4, xn + (size_t)idx * 4);
            }
            cp_commit();
        }
        __syncthreads();

        // 4x4 register-tiled dot with packed f32x2 FMAs; W from registers.
        unsigned long long acc[4][4];
        #pragma unroll
        for (int i = 0; i < 4; i++)
            #pragma unroll
            for (int j = 0; j < 4; j++) acc[i][j] = 0ull;

        #pragma unroll
        for (int k = 0; k < 4; ++k) {
            ulonglong2 sv[4];
            #pragma unroll
            for (int i = 0; i < 4; i++)
                sv[i] = *(const ulonglong2*)(sb + (bt + i) * D_DIM + l64 * 4 + k * 256);
            #pragma unroll
            for (int i = 0; i < 4; i++)
                #pragma unroll
                for (int j = 0; j < 4; j++) {
                    ffma2(acc[i][j], sv[i].x, wreg[k][j][0]);
                    ffma2(acc[i][j], sv[i].y, wreg[k][j][1]);
                }
        }

        // Reduce across the 32 lanes of each warp.
        #pragma unroll
        for (int i = 0; i < 4; i++)
            #pragma unroll
            for (int j = 0; j < 4; j++) {
                float v = unpack_sum(acc[i][j]);
                #pragma unroll
                for (int off = 16; off; off >>= 1)
                    v += __shfl_down_sync(0xffffffffu, v, off);
                if ((tid & 31) == 0)
                    red_s[tile * 32 + wit * 16 + i * 4 + j] = v;
            }
        __syncthreads();

        // Final combine + h store (coalesced in e within each 8-thread group).
        if (tid < 64) {
            int b  = tid >> 3;
            int el = tid & 7;
            int tl = ((b >> 2) & 1) | (((el >> 2) & 1) << 1);
            int ij = (b & 3) * 4 + (el & 3);
            float h = red_s[tl * 32 + ij] + red_s[tl * 32 + 16 + ij] + bias_s[el];
            out_h[(size_t)(t + 1) * (B_DIM * D_DIM) + b * D_DIM + e0 + el] = h;
        }
        __syncthreads();
        if (tid == 0) st_release(&g_flag[t][blockIdx.x], 1);
        buf ^= 1;
    }
}

// ------------------------- silu epilogue (parallel) --------------------------
__global__ void silu_kernel(const float* __restrict__ h1, float* __restrict__ out) {
    int i = blockIdx.x * blockDim.x + threadIdx.x;   // over T*B*D/4 float4
    float4 v = ((const float4*)h1)[i];
    v.x = v.x / (1.f + expf(-v.x));
    v.y = v.y / (1.f + expf(-v.y));
    v.z = v.z / (1.f + expf(-v.z));
    v.w = v.w / (1.f + expf(-v.w));
    ((float4*)out)[i] = v;
}

// ------------------------------- launcher ------------------------------------
extern "C" void kernel_launch(void* const* d_in, const int* in_sizes, int n_in,
                              void* d_out, int out_size) {
    const float* x  = (const float*)d_in[0];   // [T, B, D]
    const float* h0 = (const float*)d_in[1];   // [B, D]
    const float* W  = (const float*)d_in[2];   // [D, D]
    const float* bv = (const float*)d_in[3];   // [D]
    const float* u  = (const float*)d_in[4];   // [D]

    float* out_silu = (float*)d_out;                                  // [T, B, D]
    float* out_h    = (float*)d_out + (size_t)T_DIM * B_DIM * D_DIM;  // [T+1, B, D]

    // Reset flags (captured memset each replay).
    void* flag_addr = nullptr;
    cudaGetSymbolAddress(&flag_addr, g_flag);
    cudaMemsetAsync(flag_addr, 0, sizeof(int) * T_DIM * NCTA, 0);

    // h[0] = h0
    cudaMemcpyAsync(out_h, h0, sizeof(float) * B_DIM * D_DIM,
                    cudaMemcpyDeviceToDevice, 0);

    // Power iteration (unnormalized vectors + scalar chain).
    float* p = nullptr;
    cudaGetSymbolAddress((void**)&p, g_p);
    mv_T_kernel<<<128, 256>>>(W, u, p + 0 * D_DIM);
    mv_N_kernel<<<128, 256>>>(W, p + 0 * D_DIM, p + 1 * D_DIM);
    mv_T_kernel<<<128, 256>>>(W, p + 1 * D_DIM, p + 2 * D_DIM);
    mv_N_kernel<<<128, 256>>>(W, p + 2 * D_DIM, p + 3 * D_DIM);
    mv_T_kernel<<<128, 256>>>(W, p + 3 * D_DIM, p + 4 * D_DIM);
    mv_N_kernel<<<128, 256>>>(W, p + 4 * D_DIM, p + 5 * D_DIM);
    finalize_kernel<<<1, 256>>>();

    // Persistent sequential scan (writes h[1..T]).
    size_t smem = (size_t)(2 * B_DIM * D_DIM + 128) * sizeof(float);
    cudaFuncSetAttribute(scan_kernel, cudaFuncAttributeMaxDynamicSharedMemorySize,
                         (int)smem);
    scan_kernel<<<NCTA, 256, smem>>>(x, W, bv, out_h);

    // output = silu(h[1..T]) — embarrassingly parallel epilogue.
    int n4 = T_DIM * B_DIM * D_DIM / 4;
    silu_kernel<<<n4 / 256, 256>>>(out_h + B_DIM * D_DIM, out_silu);
}

// round 6
// speedup vs baseline: 6.3012x; 6.3012x over previous
#include <cuda_runtime.h>
#include <cuda_bf16.h>
#include <cstdint>
#include <stdint.h>
#include <math.h>

#define D_DIM 1024
#define B_DIM 8
#define T_DIM 1024
#define L_CH 8
#define DD (1024*1024)
#define SPECTRAL_RADIUS 0.999f
#define EPS_F 1e-8f

// GEMM tiling: CTA tile 64(M) x 128(N), K-chunk 32, double buffered.
#define MT 64
#define NT 128
#define KC 32
#define LDS_STRIDE 40                       // bf16 elements per smem row (pad 8)
#define A_BYTES (MT * LDS_STRIDE * 2)       // 5120
#define B_BYTES (NT * LDS_STRIDE * 2)       // 10240
#define STAGE_BYTES (2 * A_BYTES + 2 * B_BYTES)  // Ah,Al,Bh,Bl = 30720
#define GEMM_SMEM (2 * STAGE_BYTES)

// ------------------------- device scratch ------------------------------------
__device__ float g_p[6][D_DIM];
__device__ float g_scale;
__device__ __align__(256) __nv_bfloat16 g_Wh[DD], g_Wl[DD], g_WTh[DD], g_WTl[DD];
__device__ __align__(256) __nv_bfloat16 g_Ph[DD], g_Pl[DD], g_PTh[DD], g_PTl[DD];
__device__ __align__(256) __nv_bfloat16 g_Ah[DD], g_Al[DD];
__device__ __align__(256) float g_pow[DD], g_S[2][DD], g_V[DD];

// ------------------------- PTX helpers ---------------------------------------
__device__ __forceinline__ unsigned smem_u32(const void* p) {
    unsigned a;
    asm("{ .reg .u64 t; cvta.to.shared.u64 t, %1; cvt.u32.u64 %0, t; }" : "=r"(a) : "l"(p));
    return a;
}
__device__ __forceinline__ void cp16(void* s, const void* g) {
    unsigned sa = smem_u32(s);
    asm volatile("cp.async.cg.shared.global [%0], [%1], 16;" :: "r"(sa), "l"(g));
}
__device__ __forceinline__ void cp_commit() { asm volatile("cp.async.commit_group;"); }
__device__ __forceinline__ void cp_wait0()  { asm volatile("cp.async.wait_group 0;" ::: "memory"); }
__device__ __forceinline__ void cp_wait1()  { asm volatile("cp.async.wait_group 1;" ::: "memory"); }

__device__ __forceinline__ unsigned lds_u32(const char* base, int byte_off) {
    return *(const unsigned*)(base + byte_off);
}
__device__ __forceinline__ void mma16816(float* c, unsigned a0, unsigned a1,
                                         unsigned a2, unsigned a3,
                                         unsigned b0, unsigned b1) {
    asm volatile(
        "mma.sync.aligned.m16n8k16.row.col.f32.bf16.bf16.f32 "
        "{%0,%1,%2,%3}, {%4,%5,%6,%7}, {%8,%9}, {%0,%1,%2,%3};"
        : "+f"(c[0]), "+f"(c[1]), "+f"(c[2]), "+f"(c[3])
        : "r"(a0), "r"(a1), "r"(a2), "r"(a3), "r"(b0), "r"(b1));
}

// ------------------------- power iteration ------------------------------------
__global__ void mv_T_kernel(const float* __restrict__ W, const float* __restrict__ vin,
                            float* __restrict__ vout) {
    int dl = threadIdx.x >> 5, lane = threadIdx.x & 31;
    int d = blockIdx.x * 8 + dl;
    float acc = 0.f;
    for (int e = lane; e < D_DIM; e += 32)
        acc += W[(size_t)e * D_DIM + d] * vin[e];
    #pragma unroll
    for (int off = 16; off; off >>= 1) acc += __shfl_down_sync(0xffffffffu, acc, off);
    if (lane == 0) vout[d] = acc;
}
__global__ void mv_N_kernel(const float* __restrict__ W, const float* __restrict__ vin,
                            float* __restrict__ vout) {
    int el = threadIdx.x >> 5, lane = threadIdx.x & 31;
    int e = blockIdx.x * 8 + el;
    float acc = 0.f;
    const float* row = W + (size_t)e * D_DIM;
    for (int d = lane; d < D_DIM; d += 32) acc += row[d] * vin[d];
    #pragma unroll
    for (int off = 16; off; off >>= 1) acc += __shfl_down_sync(0xffffffffu, acc, off);
    if (lane == 0) vout[e] = acc;
}
__global__ void finalize_kernel() {
    __shared__ float red[256];
    __shared__ float ssq[6];
    int tid = threadIdx.x;
    for (int v = 0; v < 6; v++) {
        float local = 0.f;
        for (int i = tid; i < D_DIM; i += 256) { float x = g_p[v][i]; local += x * x; }
        red[tid] = local;
        __syncthreads();
        for (int s = 128; s; s >>= 1) { if (tid < s) red[tid] += red[tid + s]; __syncthreads(); }
        if (tid == 0) ssq[v] = red[0];
        __syncthreads();
    }
    if (tid == 0) {
        float a1 = 1.f / (sqrtf(ssq[0]) + EPS_F);
        float b1 = a1 / (a1 * sqrtf(ssq[1]) + EPS_F);
        float a2 = b1 / (b1 * sqrtf(ssq[2]) + EPS_F);
        float b2 = a2 / (a2 * sqrtf(ssq[3]) + EPS_F);
        float a3 = b2 / (b2 * sqrtf(ssq[4]) + EPS_F);
        float b3 = a3 / (a3 * sqrtf(ssq[5]) + EPS_F);
        float sigma = fabsf(a3 * b3 * ssq[5]);
        g_scale = SPECTRAL_RADIUS / (sigma + EPS_F);
    }
}

// --------------------- split (+ transpose) kernel -----------------------------
__global__ void split_tr_kernel(const float* __restrict__ in, int useScale,
                                __nv_bfloat16* __restrict__ oh, __nv_bfloat16* __restrict__ ol,
                                __nv_bfloat16* __restrict__ oth, __nv_bfloat16* __restrict__ otl) {
    __shared__ float tile[32][33];
    float s = useScale ? g_scale : 1.0f;
    int bx = blockIdx.x, by = blockIdx.y;
    int tx = threadIdx.x, ty = threadIdx.y;     // 32 x 8
    #pragma unroll
    for (int k = 0; k < 4; k++) {
        int r = by * 32 + ty + k * 8, c = bx * 32 + tx;
        float v = in[(size_t)r * D_DIM + c] * s;
        tile[ty + k * 8][tx] = v;
        __nv_bfloat16 h = __float2bfloat16(v);
        oh[(size_t)r * D_DIM + c] = h;
        ol[(size_t)r * D_DIM + c] = __float2bfloat16(v - __bfloat162float(h));
    }
    __syncthreads();
    #pragma unroll
    for (int k = 0; k < 4; k++) {
        int rt = bx * 32 + ty + k * 8, ct = by * 32 + tx;
        float v = tile[tx][ty + k * 8];
        __nv_bfloat16 h = __float2bfloat16(v);
        oth[(size_t)rt * D_DIM + ct] = h;
        otl[(size_t)rt * D_DIM + ct] = __float2bfloat16(v - __bfloat162float(h));
    }
}

// ------------------------- elementwise prep kernels ---------------------------
__device__ __forceinline__ void wr_split(size_t gid, float v,
                                         __nv_bfloat16* ah, __nv_bfloat16* al) {
    __nv_bfloat16 h = __float2bfloat16(v);
    ah[gid] = h;
    al[gid] = __float2bfloat16(v - __bfloat162float(h));
}

__global__ void prep1_kernel(const float* __restrict__ x, const float* __restrict__ h0,
                             const float* __restrict__ hbuf, int j,
                             __nv_bfloat16* __restrict__ ah, __nv_bfloat16* __restrict__ al) {
    size_t gid = (size_t)blockIdx.x * 256 + threadIdx.x;
    int m = (int)(gid >> 10), d = (int)(gid & 1023);
    int c = m >> 3, b = m & 7;
    int t = c * L_CH + j;
    float v = x[((size_t)t * B_DIM + b) * D_DIM + d];
    if (j > 0)       v += hbuf[((size_t)t * B_DIM + b) * D_DIM + d];
    else if (c == 0) v += h0[(size_t)b * D_DIM + d];
    wr_split(gid, v, ah, al);
}

__global__ void copyP0_kernel(const float* __restrict__ hbuf, float* __restrict__ S0) {
    size_t gid = (size_t)blockIdx.x * 256 + threadIdx.x;
    int m = (int)(gid >> 10), d = (int)(gid & 1023);
    int c = m >> 3, b = m & 7;
    S0[gid] = hbuf[((size_t)(c * L_CH + 8) * B_DIM + b) * D_DIM + d];
}

__global__ void prep_scan_kernel(const float* __restrict__ S, int shift,
                                 __nv_bfloat16* __restrict__ ah, __nv_bfloat16* __restrict__ al) {
    size_t gid = (size_t)blockIdx.x * 256 + threadIdx.x;
    int m = (int)(gid >> 10), d = (int)(gid & 1023);
    int c = m >> 3;
    float v = (c >= shift) ? S[(size_t)(m - shift * B_DIM) * D_DIM + d] : 0.f;
    wr_split(gid, v, ah, al);
}

__global__ void prep3_kernel(const float* __restrict__ Sfin,
                             __nv_bfloat16* __restrict__ ah, __nv_bfloat16* __restrict__ al) {
    size_t gid = (size_t)blockIdx.x * 256 + threadIdx.x;
    int m = (int)(gid >> 10), d = (int)(gid & 1023);
    int c = m >> 3;
    float v = (c >= 1) ? Sfin[(size_t)(m - B_DIM) * D_DIM + d] : 0.f;
    wr_split(gid, v, ah, al);
}

__global__ void apply3_kernel(const float* __restrict__ V, float* __restrict__ hbuf, int j,
                              __nv_bfloat16* __restrict__ ah, __nv_bfloat16* __restrict__ al) {
    size_t gid = (size_t)blockIdx.x * 256 + threadIdx.x;
    int m = (int)(gid >> 10), d = (int)(gid & 1023);
    int c = m >> 3, b = m & 7;
    float v = V[gid];
    size_t slot = ((size_t)(c * L_CH + j + 1) * B_DIM + b) * D_DIM + d;
    hbuf[slot] += v;
    wr_split(gid, v, ah, al);
}

__global__ void silu_kernel(const float* __restrict__ h1, float* __restrict__ out) {
    int i = blockIdx.x * blockDim.x + threadIdx.x;
    float4 v = ((const float4*)h1)[i];
    v.x = v.x / (1.f + expf(-v.x));
    v.y = v.y / (1.f + expf(-v.y));
    v.z = v.z / (1.f + expf(-v.z));
    v.w = v.w / (1.f + expf(-v.w));
    ((float4*)out)[i] = v;
}

// ------------------------- mma.sync split-bf16 GEMM ---------------------------
// R[m,n] = sum_k A[m,k]*B[n,k], A = Ah+Al, B = Bh+Bl (3 term products).
// CTA tile 64x128, warps 2(M) x 4(N), warp tile 32x32 = 2x4 m16n8k16.
__device__ __forceinline__ void load_chunk(char* sm, int stage,
        const __nv_bfloat16* Ah, const __nv_bfloat16* Al,
        const __nv_bfloat16* Bh, const __nv_bfloat16* Bl,
        int arow0, int brow0, int kc, int tid) {
    char* sb = sm + stage * STAGE_BYTES;
    // A: 2 arrays x 64 rows x 4 (16B units) = 512 entries
    #pragma unroll
    for (int i = 0; i < 2; i++) {
        int e = tid + i * 256;
        int arr = e >> 8;            // 0 = Ah, 1 = Al
        int rr = (e & 255) >> 2;
        int cc = e & 3;
        const __nv_bfloat16* src = arr ? Al : Ah;
        cp16(sb + arr * A_BYTES + rr * (LDS_STRIDE * 2) + cc * 16,
             src + (size_t)(arow0 + rr) * D_DIM + kc * KC + cc * 8);
    }
    // B: 2 arrays x 128 rows x 4 = 1024 entries
    #pragma unroll
    for (int i = 0; i < 4; i++) {
        int e = tid + i * 256;
        int arr = e >> 9;            // 0 = Bh, 1 = Bl
        int rr = (e & 511) >> 2;
        int cc = e & 3;
        const __nv_bfloat16* src = arr ? Bl : Bh;
        cp16(sb + 2 * A_BYTES + arr * B_BYTES + rr * (LDS_STRIDE * 2) + cc * 16,
             src + (size_t)(brow0 + rr) * D_DIM + kc * KC + cc * 8);
    }
    cp_commit();
}

__global__ void __launch_bounds__(256, 1)
gemm_kernel(const __nv_bfloat16* __restrict__ Ah, const __nv_bfloat16* __restrict__ Al,
            const __nv_bfloat16* __restrict__ Bh, const __nv_bfloat16* __restrict__ Bl,
            float* __restrict__ out, const float* __restrict__ addsrc,
            const float* __restrict__ bias, int mode, int jstep) {
    extern __shared__ char sm[];
    const int tid = threadIdx.x;
    const int wid = tid >> 5, lane = tid & 31;
    const int bx = blockIdx.x, by = blockIdx.y;
    const int warp_m = wid >> 2, warp_n = wid & 3;
    const int g = lane >> 2, tg = lane & 3;      // mma group / thread-in-group

    int arow0 = by * MT, brow0 = bx * NT;

    float acc[2][4][4];
    #pragma unroll
    for (int i = 0; i < 2; i++)
        #pragma unroll
        for (int j = 0; j < 4; j++)
            #pragma unroll
            for (int q = 0; q < 4; q++) acc[i][j][q] = 0.f;

    load_chunk(sm, 0, Ah, Al, Bh, Bl, arow0, brow0, 0, tid);

    const int NKC = D_DIM / KC;   // 32
    for (int kc = 0; kc < NKC; kc++) {
        int st = kc & 1;
        if (kc + 1 < NKC) {
            load_chunk(sm, st ^ 1, Ah, Al, Bh, Bl, arow0, brow0, kc + 1, tid);
            cp_wait1();
        } else {
            cp_wait0();
        }
        __syncthreads();

        const char* sA = sm + st * STAGE_BYTES;
        const char* sB = sA + 2 * A_BYTES;
        #pragma unroll
        for (int ks = 0; ks < 2; ks++) {
            int kb = (tg * 2 + ks * 16) * 2;     // byte offset of k element
            unsigned ah[2][4], al[2][4], bh[4][2], bl[4][2];
            #pragma unroll
            for (int i = 0; i < 2; i++) {
                int r = warp_m * 32 + i * 16 + g;
                int ro = r * (LDS_STRIDE * 2);
                ah[i][0] = lds_u32(sA, ro + kb);
                ah[i][1] = lds_u32(sA, ro + 8 * (LDS_STRIDE * 2) + kb);
                ah[i][2] = lds_u32(sA, ro + kb + 16);
                ah[i][3] = lds_u32(sA, ro + 8 * (LDS_STRIDE * 2) + kb + 16);
                al[i][0] = lds_u32(sA, A_BYTES + ro + kb);
                al[i][1] = lds_u32(sA, A_BYTES + ro + 8 * (LDS_STRIDE * 2) + kb);
                al[i][2] = lds_u32(sA, A_BYTES + ro + kb + 16);
                al[i][3] = lds_u32(sA, A_BYTES + ro + 8 * (LDS_STRIDE * 2) + kb + 16);
            }
            #pragma unroll
            for (int j = 0; j < 4; j++) {
                int n = warp_n * 32 + j * 8 + g;
                int no = n * (LDS_STRIDE * 2);
                bh[j][0] = lds_u32(sB, no + kb);
                bh[j][1] = lds_u32(sB, no + kb + 16);
                bl[j][0] = lds_u32(sB, B_BYTES + no + kb);
                bl[j][1] = lds_u32(sB, B_BYTES + no + kb + 16);
            }
            #pragma unroll
            for (int i = 0; i < 2; i++)
                #pragma unroll
                for (int j = 0; j < 4; j++) {
                    mma16816(acc[i][j], ah[i][0], ah[i][1], ah[i][2], ah[i][3],
                             bh[j][0], bh[j][1]);
                    mma16816(acc[i][j], ah[i][0], ah[i][1], ah[i][2], ah[i][3],
                             bl[j][0], bl[j][1]);
                    mma16816(acc[i][j], al[i][0], al[i][1], al[i][2], al[i][3],
                             bh[j][0], bh[j][1]);
                }
        }
        __syncthreads();
    }

    // Epilogue: c0,c1 -> (row, col..col+1); c2,c3 -> (row+8, ...)
    #pragma unroll
    for (int i = 0; i < 2; i++) {
        #pragma unroll
        for (int j = 0; j < 4; j++) {
            int row = by * MT + warp_m * 32 + i * 16 + g;
            int col = bx * NT + warp_n * 32 + j * 8 + tg * 2;
            #pragma unroll
            for (int half = 0; half < 2; half++) {
                int r = row + half * 8;
                float2 v;
                v.x = acc[i][j][half * 2 + 0];
                v.y = acc[i][j][half * 2 + 1];
                if (addsrc) {
                    float2 a2 = *(const float2*)(addsrc + (size_t)r * D_DIM + col);
                    v.x += a2.x; v.y += a2.y;
                }
                if (bias) {
                    float2 b2 = *(const float2*)(bias + col);
                    v.x += b2.x; v.y += b2.y;
                }
                float* dst;
                if (mode == 0) {
                    dst = out + (size_t)r * D_DIM + col;
                } else {
                    int c = r >> 3, b = r & 7;
                    dst = out + ((size_t)(c * L_CH + jstep + 1) * B_DIM + b) * D_DIM + col;
                }
                *(float2*)dst = v;
            }
        }
    }
}

// ------------------------------- launcher ------------------------------------
extern "C" void kernel_launch(void* const* d_in, const int* in_sizes, int n_in,
                              void* d_out, int out_size) {
    const float* x  = (const float*)d_in[0];
    const float* h0 = (const float*)d_in[1];
    const float* W  = (const float*)d_in[2];
    const float* bv = (const float*)d_in[3];
    const float* u  = (const float*)d_in[4];

    float* out_silu = (float*)d_out;
    float* out_h    = (float*)d_out + (size_t)T_DIM * B_DIM * D_DIM;  // h[0..T]

    float *p, *pow_, *S0, *S1, *V;
    __nv_bfloat16 *Wh, *Wl, *WTh, *WTl, *Ph, *Pl, *PTh, *PTl, *Ahh, *All;
    cudaGetSymbolAddress((void**)&p, g_p);
    cudaGetSymbolAddress((void**)&pow_, g_pow);
    cudaGetSymbolAddress((void**)&S0, g_S);   S1 = S0 + DD;
    cudaGetSymbolAddress((void**)&V, g_V);
    cudaGetSymbolAddress((void**)&Wh, g_Wh);   cudaGetSymbolAddress((void**)&Wl, g_Wl);
    cudaGetSymbolAddress((void**)&WTh, g_WTh); cudaGetSymbolAddress((void**)&WTl, g_WTl);
    cudaGetSymbolAddress((void**)&Ph, g_Ph);   cudaGetSymbolAddress((void**)&Pl, g_Pl);
    cudaGetSymbolAddress((void**)&PTh, g_PTh); cudaGetSymbolAddress((void**)&PTl, g_PTl);
    cudaGetSymbolAddress((void**)&Ahh, g_Ah);  cudaGetSymbolAddress((void**)&All, g_Al);

    cudaFuncSetAttribute(gemm_kernel, cudaFuncAttributeMaxDynamicSharedMemorySize,
                         GEMM_SMEM);

    // h[0] = h0
    cudaMemcpyAsync(out_h, h0, sizeof(float) * B_DIM * D_DIM, cudaMemcpyDeviceToDevice, 0);

    // ---- spectral scale ----
    mv_T_kernel<<<128, 256>>>(W, u, p + 0 * D_DIM);
    mv_N_kernel<<<128, 256>>>(W, p + 0 * D_DIM, p + 1 * D_DIM);
    mv_T_kernel<<<128, 256>>>(W, p + 1 * D_DIM, p + 2 * D_DIM);
    mv_N_kernel<<<128, 256>>>(W, p + 2 * D_DIM, p + 3 * D_DIM);
    mv_T_kernel<<<128, 256>>>(W, p + 3 * D_DIM, p + 4 * D_DIM);
    mv_N_kernel<<<128, 256>>>(W, p + 4 * D_DIM, p + 5 * D_DIM);
    finalize_kernel<<<1, 256>>>();

    dim3 trg(32, 32), trb(32, 8);
    dim3 gg(D_DIM / NT, D_DIM / MT);   // (8, 16)
    split_tr_kernel<<<trg, trb>>>(W, 1, Wh, Wl, WTh, WTl);

    // ---- phase 1: 8 sequential GEMMs, M = C*B = 1024 ----
    for (int j = 0; j < L_CH; j++) {
        prep1_kernel<<<4096, 256>>>(x, h0, out_h, j, Ahh, All);
        gemm_kernel<<<gg, 256, GEMM_SMEM>>>(Ahh, All, Wh, Wl, out_h, nullptr, bv, 1, j);
    }
    copyP0_kernel<<<4096, 256>>>(out_h, S0);

    // ---- squarings to A^8 ----
    gemm_kernel<<<gg, 256, GEMM_SMEM>>>(Wh, Wl, WTh, WTl, pow_, nullptr, nullptr, 0, 0);
    split_tr_kernel<<<trg, trb>>>(pow_, 0, Ph, Pl, PTh, PTl);
    gemm_kernel<<<gg, 256, GEMM_SMEM>>>(Ph, Pl, PTh, PTl, pow_, nullptr, nullptr, 0, 0);
    split_tr_kernel<<<trg, trb>>>(pow_, 0, Ph, Pl, PTh, PTl);
    gemm_kernel<<<gg, 256, GEMM_SMEM>>>(Ph, Pl, PTh, PTl, pow_, nullptr, nullptr, 0, 0);
    split_tr_kernel<<<trg, trb>>>(pow_, 0, Ph, Pl, PTh, PTl);

    // ---- boundary doubling scan: 7 rounds ----
    float* Scur = S0;
    float* Snxt = S1;
    for (int r = 0; r < 7; r++) {
        prep_scan_kernel<<<4096, 256>>>(Scur, 1 << r, Ahh, All);
        gemm_kernel<<<gg, 256, GEMM_SMEM>>>(Ahh, All, Ph, Pl, Snxt, Scur, nullptr, 0, 0);
        float* tmp = Scur; Scur = Snxt; Snxt = tmp;
        if (r < 6) {
            gemm_kernel<<<gg, 256, GEMM_SMEM>>>(Ph, Pl, PTh, PTl, pow_, nullptr, nullptr, 0, 0);
            split_tr_kernel<<<trg, trb>>>(pow_, 0, Ph, Pl, PTh, PTl);
        }
    }

    // ---- phase 3: fixup, 8 sequential GEMMs ----
    prep3_kernel<<<4096, 256>>>(Scur, Ahh, All);
    for (int j = 0; j < L_CH; j++) {
        gemm_kernel<<<gg, 256, GEMM_SMEM>>>(Ahh, All, Wh, Wl, V, nullptr, nullptr, 0, 0);
        apply3_kernel<<<4096, 256>>>(V, out_h, j, Ahh, All);
    }

    // ---- silu epilogue ----
    int n4 = T_DIM * B_DIM * D_DIM / 4;
    silu_kernel<<<n4 / 256, 256>>>(out_h + B_DIM * D_DIM, out_silu);
}

// round 7
// speedup vs baseline: 6.3823x; 1.0129x over previous
#include <cuda_runtime.h>
#include <cuda_bf16.h>
#include <cstdint>
#include <stdint.h>
#include <math.h>

#define D_DIM 1024
#define B_DIM 8
#define T_DIM 1024
#define L_CH 8
#define DD (1024*1024)
#define SPECTRAL_RADIUS 0.999f
#define EPS_F 1e-8f

// GEMM tiling: CTA tile 64(M) x 128(N), K-chunk 32, double buffered.
#define MT 64
#define NT 128
#define KC 32
#define RB 80                               // smem row bytes (40 bf16, pad 8)
#define A_BYTES (MT * RB)                   // 5120
#define B_BYTES (NT * RB)                   // 10240
#define STAGE_BYTES (2 * A_BYTES + 2 * B_BYTES)  // 30720
#define GEMM_SMEM (2 * STAGE_BYTES)

// ------------------------- device scratch ------------------------------------
__device__ float g_p[6][D_DIM];
__device__ float g_scale;
__device__ __align__(256) __nv_bfloat16 g_Wh[DD], g_Wl[DD], g_WTh[DD], g_WTl[DD];
__device__ __align__(256) __nv_bfloat16 g_Ph[DD], g_Pl[DD], g_PTh[DD], g_PTl[DD];
__device__ __align__(256) __nv_bfloat16 g_Ah[DD], g_Al[DD];      // split pair 0
__device__ __align__(256) __nv_bfloat16 g_Ch[DD], g_Cl[DD];      // split pair 1
__device__ __align__(256) float g_pow[DD], g_S[2][DD];

// ------------------------- PTX helpers ---------------------------------------
__device__ __forceinline__ unsigned smem_u32(const void* p) {
    unsigned a;
    asm("{ .reg .u64 t; cvta.to.shared.u64 t, %1; cvt.u32.u64 %0, t; }" : "=r"(a) : "l"(p));
    return a;
}
__device__ __forceinline__ void cp16(unsigned sa, const void* g) {
    asm volatile("cp.async.cg.shared.global [%0], [%1], 16;" :: "r"(sa), "l"(g));
}
__device__ __forceinline__ void cp16z(unsigned sa, const void* g, int srcsize) {
    asm volatile("cp.async.cg.shared.global [%0], [%1], 16, %2;"
                 :: "r"(sa), "l"(g), "r"(srcsize));
}
__device__ __forceinline__ void cp_commit() { asm volatile("cp.async.commit_group;"); }
__device__ __forceinline__ void cp_wait0()  { asm volatile("cp.async.wait_group 0;" ::: "memory"); }

__device__ __forceinline__ void ldsm4(unsigned addr, unsigned* r) {
    asm volatile("ldmatrix.sync.aligned.m8n8.x4.shared.b16 {%0,%1,%2,%3}, [%4];"
                 : "=r"(r[0]), "=r"(r[1]), "=r"(r[2]), "=r"(r[3]) : "r"(addr));
}
__device__ __forceinline__ void mma16816(float* c, const unsigned* a,
                                         unsigned b0, unsigned b1) {
    asm volatile(
        "mma.sync.aligned.m16n8k16.row.col.f32.bf16.bf16.f32 "
        "{%0,%1,%2,%3}, {%4,%5,%6,%7}, {%8,%9}, {%0,%1,%2,%3};"
        : "+f"(c[0]), "+f"(c[1]), "+f"(c[2]), "+f"(c[3])
        : "r"(a[0]), "r"(a[1]), "r"(a[2]), "r"(a[3]), "r"(b0), "r"(b1));
}

// ------------------------- power iteration ------------------------------------
__global__ void mv_T_kernel(const float* __restrict__ W, const float* __restrict__ vin,
                            float* __restrict__ vout) {
    int dl = threadIdx.x >> 5, lane = threadIdx.x & 31;
    int d = blockIdx.x * 8 + dl;
    float acc = 0.f;
    for (int e = lane; e < D_DIM; e += 32)
        acc += W[(size_t)e * D_DIM + d] * vin[e];
    #pragma unroll
    for (int off = 16; off; off >>= 1) acc += __shfl_down_sync(0xffffffffu, acc, off);
    if (lane == 0) vout[d] = acc;
}
__global__ void mv_N_kernel(const float* __restrict__ W, const float* __restrict__ vin,
                            float* __restrict__ vout) {
    int el = threadIdx.x >> 5, lane = threadIdx.x & 31;
    int e = blockIdx.x * 8 + el;
    float acc = 0.f;
    const float* row = W + (size_t)e * D_DIM;
    for (int d = lane; d < D_DIM; d += 32) acc += row[d] * vin[d];
    #pragma unroll
    for (int off = 16; off; off >>= 1) acc += __shfl_down_sync(0xffffffffu, acc, off);
    if (lane == 0) vout[e] = acc;
}
__global__ void finalize_kernel() {
    __shared__ float red[256];
    __shared__ float ssq[6];
    int tid = threadIdx.x;
    for (int v = 0; v < 6; v++) {
        float local = 0.f;
        for (int i = tid; i < D_DIM; i += 256) { float x = g_p[v][i]; local += x * x; }
        red[tid] = local;
        __syncthreads();
        for (int s = 128; s; s >>= 1) { if (tid < s) red[tid] += red[tid + s]; __syncthreads(); }
        if (tid == 0) ssq[v] = red[0];
        __syncthreads();
    }
    if (tid == 0) {
        float a1 = 1.f / (sqrtf(ssq[0]) + EPS_F);
        float b1 = a1 / (a1 * sqrtf(ssq[1]) + EPS_F);
        float a2 = b1 / (b1 * sqrtf(ssq[2]) + EPS_F);
        float b2 = a2 / (a2 * sqrtf(ssq[3]) + EPS_F);
        float a3 = b2 / (b2 * sqrtf(ssq[4]) + EPS_F);
        float b3 = a3 / (a3 * sqrtf(ssq[5]) + EPS_F);
        float sigma = fabsf(a3 * b3 * ssq[5]);
        g_scale = SPECTRAL_RADIUS / (sigma + EPS_F);
    }
}

// --------------------- split (+ transpose) kernel -----------------------------
__global__ void split_tr_kernel(const float* __restrict__ in, int useScale,
                                __nv_bfloat16* __restrict__ oh, __nv_bfloat16* __restrict__ ol,
                                __nv_bfloat16* __restrict__ oth, __nv_bfloat16* __restrict__ otl) {
    __shared__ float tile[32][33];
    float s = useScale ? g_scale : 1.0f;
    int bx = blockIdx.x, by = blockIdx.y;
    int tx = threadIdx.x, ty = threadIdx.y;     // 32 x 8
    #pragma unroll
    for (int k = 0; k < 4; k++) {
        int r = by * 32 + ty + k * 8, c = bx * 32 + tx;
        float v = in[(size_t)r * D_DIM + c] * s;
        tile[ty + k * 8][tx] = v;
        __nv_bfloat16 h = __float2bfloat16(v);
        oh[(size_t)r * D_DIM + c] = h;
        ol[(size_t)r * D_DIM + c] = __float2bfloat16(v - __bfloat162float(h));
    }
    __syncthreads();
    #pragma unroll
    for (int k = 0; k < 4; k++) {
        int rt = bx * 32 + ty + k * 8, ct = by * 32 + tx;
        float v = tile[tx][ty + k * 8];
        __nv_bfloat16 h = __float2bfloat16(v);
        oth[(size_t)rt * D_DIM + ct] = h;
        otl[(size_t)rt * D_DIM + ct] = __float2bfloat16(v - __bfloat162float(h));
    }
}

// ------------------------- prep for phase-1 j=0 -------------------------------
__global__ void prep1_kernel(const float* __restrict__ x, const float* __restrict__ h0,
                             __nv_bfloat16* __restrict__ ah, __nv_bfloat16* __restrict__ al) {
    size_t gid = (size_t)blockIdx.x * 256 + threadIdx.x;
    int m = (int)(gid >> 10), d = (int)(gid & 1023);
    int c = m >> 3, b = m & 7;
    int t = c * L_CH;
    float v = x[((size_t)t * B_DIM + b) * D_DIM + d];
    if (c == 0) v += h0[(size_t)b * D_DIM + d];
    __nv_bfloat16 h = __float2bfloat16(v);
    ah[gid] = h;
    al[gid] = __float2bfloat16(v - __bfloat162float(h));
}

__global__ void silu_kernel(const float* __restrict__ h1, float* __restrict__ out) {
    int i = blockIdx.x * blockDim.x + threadIdx.x;
    float4 v = ((const float4*)h1)[i];
    v.x = v.x / (1.f + expf(-v.x));
    v.y = v.y / (1.f + expf(-v.y));
    v.z = v.z / (1.f + expf(-v.z));
    v.w = v.w / (1.f + expf(-v.w));
    ((float4*)out)[i] = v;
}

// ------------------------- mma.sync split-bf16 GEMM ---------------------------
// R[m,n] = sum_k A[m+ashift,k]*B[n,k], A = Ah+Al, B = Bh+Bl (3-term split);
// rows with m+ashift < 0 are zero (cp.async zero-fill).
// CTA tile 64x128, warps 2(M) x 4(N), warp tile 32x32 = 2x4 m16n8k16.
// Epilogue modes:
//  0: out[m,n] (+addsrc) ; optional split(v) -> sh/sl
//  1: phase1: v += bias; out_h[slot(c*8+j+1)] = v; split(v + x[t+1]) (or split(v)
//     when xnext==null); optional fdst[m,n] = v
//  2: phase3: out_h[slot] += v; optional split(v)
__device__ __forceinline__ void load_chunk(unsigned smb, int stage,
        const __nv_bfloat16* Ah, const __nv_bfloat16* Al, int ashift,
        const __nv_bfloat16* Bh, const __nv_bfloat16* Bl,
        int arow0, int brow0, int kc, int tid) {
    unsigned sb = smb + stage * STAGE_BYTES;
    #pragma unroll
    for (int i = 0; i < 2; i++) {           // A: Ah,Al 64 rows x 4 x 16B
        int e = tid + i * 256;
        int arr = e >> 8;
        int rr = (e & 255) >> 2;
        int cc = e & 3;
        const __nv_bfloat16* src = arr ? Al : Ah;
        int r = arow0 + rr + ashift;
        int sz = (r >= 0) ? 16 : 0;
        if (r < 0) r = 0;
        cp16z(sb + arr * A_BYTES + rr * RB + cc * 16,
              src + (size_t)r * D_DIM + kc * KC + cc * 8, sz);
    }
    #pragma unroll
    for (int i = 0; i < 4; i++) {           // B: Bh,Bl 128 rows x 4 x 16B
        int e = tid + i * 256;
        int arr = e >> 9;
        int rr = (e & 511) >> 2;
        int cc = e & 3;
        const __nv_bfloat16* src = arr ? Bl : Bh;
        cp16(sb + 2 * A_BYTES + arr * B_BYTES + rr * RB + cc * 16,
             src + (size_t)(brow0 + rr) * D_DIM + kc * KC + cc * 8);
    }
    cp_commit();
}

__global__ void __launch_bounds__(256, 1)
gemm_kernel(const __nv_bfloat16* __restrict__ Ah, const __nv_bfloat16* __restrict__ Al,
            int ashift,
            const __nv_bfloat16* __restrict__ Bh, const __nv_bfloat16* __restrict__ Bl,
            float* __restrict__ out, const float* __restrict__ addsrc,
            const float* __restrict__ bias, const float* __restrict__ xnext,
            __nv_bfloat16* __restrict__ sh, __nv_bfloat16* __restrict__ sl,
            float* __restrict__ fdst, int emode, int jstep) {
    extern __shared__ char sm[];
    unsigned smb = smem_u32(sm);
    const int tid = threadIdx.x;
    const int wid = tid >> 5, lane = tid & 31;
    const int bx = blockIdx.x, by = blockIdx.y;
    const int warp_m = wid >> 2, warp_n = wid & 3;
    const int g = lane >> 2, tg = lane & 3;

    int arow0 = by * MT, brow0 = bx * NT;

    // ldmatrix per-lane base addresses (lanes 0-15: rows, 16-31: +16B k-half)
    unsigned lrow = lane & 15, lhalf = lane >> 4;
    unsigned aBase = smb + (warp_m * 32 + lrow) * RB + lhalf * 16;
    unsigned bBase = smb + 2 * A_BYTES + (warp_n * 32 + lrow) * RB + lhalf * 16;

    float acc[2][4][4];
    #pragma unroll
    for (int i = 0; i < 2; i++)
        #pragma unroll
        for (int j = 0; j < 4; j++)
            #pragma unroll
            for (int q = 0; q < 4; q++) acc[i][j][q] = 0.f;

    load_chunk(smb, 0, Ah, Al, ashift, Bh, Bl, arow0, brow0, 0, tid);

    const int NKC = D_DIM / KC;   // 32
    for (int kc = 0; kc < NKC; kc++) {
        int st = kc & 1;
        cp_wait0();
        __syncthreads();
        if (kc + 1 < NKC)
            load_chunk(smb, st ^ 1, Ah, Al, ashift, Bh, Bl, arow0, brow0, kc + 1, tid);

        unsigned sa = aBase + st * STAGE_BYTES;
        unsigned sb = bBase + st * STAGE_BYTES;
        #pragma unroll
        for (int ks = 0; ks < 2; ks++) {
            unsigned ko = ks * 32;
            unsigned AH0[4], AH1[4], AL0[4], AL1[4];
            ldsm4(sa + ko, AH0);
            ldsm4(sa + 16 * RB + ko, AH1);
            ldsm4(sa + A_BYTES + ko, AL0);
            ldsm4(sa + A_BYTES + 16 * RB + ko, AL1);
            unsigned BH0[4], BH1[4], BL0[4], BL1[4];
            ldsm4(sb + ko, BH0);              // n0-15  -> j0,j1
            ldsm4(sb + 16 * RB + ko, BH1);    // n16-31 -> j2,j3
            ldsm4(sb + B_BYTES + ko, BL0);
            ldsm4(sb + B_BYTES + 16 * RB + ko, BL1);

            unsigned bh[4][2] = {{BH0[0],BH0[2]},{BH0[1],BH0[3]},
                                 {BH1[0],BH1[2]},{BH1[1],BH1[3]}};
            unsigned bl[4][2] = {{BL0[0],BL0[2]},{BL0[1],BL0[3]},
                                 {BL1[0],BL1[2]},{BL1[1],BL1[3]}};
            #pragma unroll
            for (int j = 0; j < 4; j++) {
                mma16816(acc[0][j], AH0, bh[j][0], bh[j][1]);
                mma16816(acc[0][j], AH0, bl[j][0], bl[j][1]);
                mma16816(acc[0][j], AL0, bh[j][0], bh[j][1]);
                mma16816(acc[1][j], AH1, bh[j][0], bh[j][1]);
                mma16816(acc[1][j], AH1, bl[j][0], bl[j][1]);
                mma16816(acc[1][j], AL1, bh[j][0], bh[j][1]);
            }
        }
    }

    // Epilogue
    #pragma unroll
    for (int i = 0; i < 2; i++) {
        #pragma unroll
        for (int j = 0; j < 4; j++) {
            int rm = by * MT + warp_m * 32 + i * 16 + g;
            int col = bx * NT + warp_n * 32 + j * 8 + tg * 2;
            #pragma unroll
            for (int half = 0; half < 2; half++) {
                int r = rm + half * 8;
                float vx = acc[i][j][half * 2 + 0];
                float vy = acc[i][j][half * 2 + 1];
                size_t flat = (size_t)r * D_DIM + col;
                if (emode == 0) {
                    if (addsrc) {
                        float2 a2 = *(const float2*)(addsrc + flat);
                        vx += a2.x; vy += a2.y;
                    }
                    float2 o; o.x = vx; o.y = vy;
                    *(float2*)(out + flat) = o;
                    if (sh) {
                        __nv_bfloat16 hx = __float2bfloat16(vx);
                        __nv_bfloat16 hy = __float2bfloat16(vy);
                        __nv_bfloat162 h2; h2.x = hx; h2.y = hy;
                        __nv_bfloat162 l2;
                        l2.x = __float2bfloat16(vx - __bfloat162float(hx));
                        l2.y = __float2bfloat16(vy - __bfloat162float(hy));
                        *(__nv_bfloat162*)(sh + flat) = h2;
                        *(__nv_bfloat162*)(sl + flat) = l2;
                    }
                } else {
                    int c = r >> 3, b = r & 7;
                    int t1 = c * L_CH + jstep + 1;
                    size_t idx = ((size_t)t1 * B_DIM + b) * D_DIM + col;
                    if (emode == 1) {
                        float2 b2 = *(const float2*)(bias + col);
                        vx += b2.x; vy += b2.y;
                        float2 o; o.x = vx; o.y = vy;
                        *(float2*)(out + idx) = o;
                        if (fdst) { float2 f; f.x = vx; f.y = vy;
                                    *(float2*)(fdst + flat) = f; }
                        float sx = vx, sy = vy;
                        if (xnext) {
                            float2 xv = *(const float2*)(xnext + idx);
                            sx += xv.x; sy += xv.y;
                        }
                        __nv_bfloat16 hx = __float2bfloat16(sx);
                        __nv_bfloat16 hy = __float2bfloat16(sy);
                        __nv_bfloat162 h2; h2.x = hx; h2.y = hy;
                        __nv_bfloat162 l2;
                        l2.x = __float2bfloat16(sx - __bfloat162float(hx));
                        l2.y = __float2bfloat16(sy - __bfloat162float(hy));
                        *(__nv_bfloat162*)(sh + flat) = h2;
                        *(__nv_bfloat162*)(sl + flat) = l2;
                    } else {  // emode == 2
                        float2 o = *(const float2*)(out + idx);
                        o.x += vx; o.y += vy;
                        *(float2*)(out + idx) = o;
                        if (sh) {
                            __nv_bfloat16 hx = __float2bfloat16(vx);
                            __nv_bfloat16 hy = __float2bfloat16(vy);
                            __nv_bfloat162 h2; h2.x = hx; h2.y = hy;
                            __nv_bfloat162 l2;
                            l2.x = __float2bfloat16(vx - __bfloat162float(hx));
                            l2.y = __float2bfloat16(vy - __bfloat162float(hy));
                            *(__nv_bfloat162*)(sh + flat) = h2;
                            *(__nv_bfloat162*)(sl + flat) = l2;
                        }
                    }
                }
            }
        }
    }
}

// ------------------------------- launcher ------------------------------------
extern "C" void kernel_launch(void* const* d_in, const int* in_sizes, int n_in,
                              void* d_out, int out_size) {
    const float* x  = (const float*)d_in[0];
    const float* h0 = (const float*)d_in[1];
    const float* W  = (const float*)d_in[2];
    const float* bv = (const float*)d_in[3];
    const float* u  = (const float*)d_in[4];

    float* out_silu = (float*)d_out;
    float* out_h    = (float*)d_out + (size_t)T_DIM * B_DIM * D_DIM;  // h[0..T]

    float *p, *pow_, *S0, *S1;
    __nv_bfloat16 *Wh, *Wl, *WTh, *WTl, *Ph, *Pl, *PTh, *PTl;
    __nv_bfloat16 *p0h, *p0l, *p1h, *p1l;
    cudaGetSymbolAddress((void**)&p, g_p);
    cudaGetSymbolAddress((void**)&pow_, g_pow);
    cudaGetSymbolAddress((void**)&S0, g_S);   S1 = S0 + DD;
    cudaGetSymbolAddress((void**)&Wh, g_Wh);   cudaGetSymbolAddress((void**)&Wl, g_Wl);
    cudaGetSymbolAddress((void**)&WTh, g_WTh); cudaGetSymbolAddress((void**)&WTl, g_WTl);
    cudaGetSymbolAddress((void**)&Ph, g_Ph);   cudaGetSymbolAddress((void**)&Pl, g_Pl);
    cudaGetSymbolAddress((void**)&PTh, g_PTh); cudaGetSymbolAddress((void**)&PTl, g_PTl);
    cudaGetSymbolAddress((void**)&p0h, g_Ah);  cudaGetSymbolAddress((void**)&p0l, g_Al);
    cudaGetSymbolAddress((void**)&p1h, g_Ch);  cudaGetSymbolAddress((void**)&p1l, g_Cl);

    cudaFuncSetAttribute(gemm_kernel, cudaFuncAttributeMaxDynamicSharedMemorySize,
                         GEMM_SMEM);

    __nv_bfloat16* pairh[2] = {p0h, p1h};
    __nv_bfloat16* pairl[2] = {p0l, p1l};

    // h[0] = h0
    cudaMemcpyAsync(out_h, h0, sizeof(float) * B_DIM * D_DIM, cudaMemcpyDeviceToDevice, 0);

    // ---- spectral scale ----
    mv_T_kernel<<<128, 256>>>(W, u, p + 0 * D_DIM);
    mv_N_kernel<<<128, 256>>>(W, p + 0 * D_DIM, p + 1 * D_DIM);
    mv_T_kernel<<<128, 256>>>(W, p + 1 * D_DIM, p + 2 * D_DIM);
    mv_N_kernel<<<128, 256>>>(W, p + 2 * D_DIM, p + 3 * D_DIM);
    mv_T_kernel<<<128, 256>>>(W, p + 3 * D_DIM, p + 4 * D_DIM);
    mv_N_kernel<<<128, 256>>>(W, p + 4 * D_DIM, p + 5 * D_DIM);
    finalize_kernel<<<1, 256>>>();

    dim3 trg(32, 32), trb(32, 8);
    dim3 gg(D_DIM / NT, D_DIM / MT);   // (8, 16)
    split_tr_kernel<<<trg, trb>>>(W, 1, Wh, Wl, WTh, WTl);

    // ---- phase 1: 8 GEMMs; epilogue writes h slot + split(h + x_next) --------
    prep1_kernel<<<4096, 256>>>(x, h0, p0h, p0l);
    for (int j = 0; j < L_CH; j++) {
        int in = j & 1, outp = (j + 1) & 1;
        gemm_kernel<<<gg, 256, GEMM_SMEM>>>(
            pairh[in], pairl[in], 0, Wh, Wl, out_h, nullptr, bv,
            (j < 7) ? x : nullptr, pairh[outp], pairl[outp],
            (j == 7) ? S0 : nullptr, 1, j);
    }

    // ---- squarings to A^8 ----
    gemm_kernel<<<gg, 256, GEMM_SMEM>>>(Wh, Wl, 0, WTh, WTl, pow_, nullptr, nullptr,
                                        nullptr, nullptr, nullptr, nullptr, 0, 0);
    split_tr_kernel<<<trg, trb>>>(pow_, 0, Ph, Pl, PTh, PTl);
    gemm_kernel<<<gg, 256, GEMM_SMEM>>>(Ph, Pl, 0, PTh, PTl, pow_, nullptr, nullptr,
                                        nullptr, nullptr, nullptr, nullptr, 0, 0);
    split_tr_kernel<<<trg, trb>>>(pow_, 0, Ph, Pl, PTh, PTl);
    gemm_kernel<<<gg, 256, GEMM_SMEM>>>(Ph, Pl, 0, PTh, PTl, pow_, nullptr, nullptr,
                                        nullptr, nullptr, nullptr, nullptr, 0, 0);
    split_tr_kernel<<<trg, trb>>>(pow_, 0, Ph, Pl, PTh, PTl);

    // ---- boundary doubling scan: 7 rounds; shift folded into A-loads ---------
    float* Sc = S0;
    float* Sn = S1;
    for (int r = 0; r < 7; r++) {
        int in = r & 1, outp = (r + 1) & 1;
        gemm_kernel<<<gg, 256, GEMM_SMEM>>>(
            pairh[in], pairl[in], -(1 << r) * B_DIM, Ph, Pl, Sn, Sc, nullptr,
            nullptr, pairh[outp], pairl[outp], nullptr, 0, 0);
        float* tmp = Sc; Sc = Sn; Sn = tmp;
        if (r < 6) {
            gemm_kernel<<<gg, 256, GEMM_SMEM>>>(Ph, Pl, 0, PTh, PTl, pow_, nullptr,
                                                nullptr, nullptr, nullptr, nullptr,
                                                nullptr, 0, 0);
            split_tr_kernel<<<trg, trb>>>(pow_, 0, Ph, Pl, PTh, PTl);
        }
    }

    // ---- phase 3: fixup; epilogue accumulates into h slots -------------------
    for (int j = 0; j < L_CH; j++) {
        int in = (j + 1) & 1, outp = j & 1;
        gemm_kernel<<<gg, 256, GEMM_SMEM>>>(
            pairh[in], pairl[in], (j == 0) ? -B_DIM : 0, Wh, Wl, out_h, nullptr,
            nullptr, nullptr, (j < 7) ? pairh[outp] : nullptr,
            (j < 7) ? pairl[outp] : nullptr, nullptr, 2, j);
    }

    // ---- silu epilogue ----
    int n4 = T_DIM * B_DIM * D_DIM / 4;
    silu_kernel<<<n4 / 256, 256>>>(out_h + B_DIM * D_DIM, out_silu);
}